// round 4
// baseline (speedup 1.0000x reference)
#include <cuda_runtime.h>
#include <cuda_bf16.h>

#define NMAX   100000
#define EMAX   1600000
#define CIN_   128
#define COUT_  64
#define CAP    80          // max bucketed degree (P(overflow) ~ 1e-29/node)
#define SPILLMAX 8192

// Scratch (device globals — no allocation allowed).
// Invariants at kernel_launch entry (restored by the kernels themselves each
// call; static zero-init on first call): g_deg == 0, g_spill_n == 0.
__device__ float g_H[NMAX * COUT_];
__device__ float g_dinv[NMAX];
__device__ int   g_deg[NMAX];
__device__ int   g_edgeb[NMAX * CAP];     // src per slot, bucketed by dst
__device__ int2  g_spill[SPILLMAX];       // {dst, src} overflow edges
__device__ int   g_spill_n;
__device__ int   g_spill_n2;

// ---------------------------------------------------------------------------
// A) fused kernel, role split by blockIdx%3:
//    roles 0,1 -> GEMM tile (FMA pipe);  role 2 -> edge bucketing (LTS pipe)
// ---------------------------------------------------------------------------
#define FMA2(d, a, b) asm("fma.rn.f32x2 %0, %1, %2, %3;" \
                          : "=l"(d) : "l"(a), "l"(b), "l"(d))

__global__ __launch_bounds__(256) void fused_kernel(
    const float* __restrict__ X, const float* __restrict__ W,
    const float* __restrict__ bias,
    const int* __restrict__ src, const int* __restrict__ dst,
    int n, int E, int NG, int NE)
{
    const int idx = blockIdx.x;
    const int r3  = idx % 3;

    if (r3 == 2) {
        // ---- edge role: degree count + bucket fill ----
        int cid   = idx / 3;
        int chunk = (E + NE - 1) / NE;
        int e0    = cid * chunk;
        int e1    = min(e0 + chunk, E);
        for (int i = e0 + threadIdx.x; i < e1; i += 256) {
            int d = __ldg(&dst[i]);
            int s = __ldg(&src[i]);
            int pos = atomicAdd(&g_deg[d], 1);
            if (pos < CAP) {
                g_edgeb[d * CAP + pos] = s;
            } else {
                int q = atomicAdd(&g_spill_n, 1);
                if (q < SPILLMAX) g_spill[q] = make_int2(d, s);
            }
        }
        return;
    }

    // ---- GEMM role: tile of 128 rows x 64 cols, packed f32x2 FMA ----
    const int tile = (idx / 3) * 2 + r3;
    if (tile >= NG) return;

    __shared__ float2 Xs2[16][130];   // duplicated (x,x) pairs
    __shared__ float  Ws[16][64];

    const int tid  = threadIdx.x;
    const int tcol = tid & 15;        // cols tcol*4 .. +3
    const int trow = tid >> 4;        // rows trow*8 .. +7
    const int row0 = tile * 128;

    unsigned long long acc[8][2];
    #pragma unroll
    for (int r = 0; r < 8; r++) { acc[r][0] = 0ull; acc[r][1] = 0ull; }

    for (int k0 = 0; k0 < CIN_; k0 += 16) {
        #pragma unroll
        for (int p = 0; p < 2; p++) {
            int r  = p * 64 + (tid >> 2);
            int kq = tid & 3;
            int rr = row0 + r;
            const float* xp = X + (long)(rr < n ? rr : 0) * CIN_ + k0 + kq * 4;
            float4 v = *(const float4*)xp;
            Xs2[kq * 4 + 0][r] = make_float2(v.x, v.x);
            Xs2[kq * 4 + 1][r] = make_float2(v.y, v.y);
            Xs2[kq * 4 + 2][r] = make_float2(v.z, v.z);
            Xs2[kq * 4 + 3][r] = make_float2(v.w, v.w);
        }
        {
            int k    = tid >> 4;
            int colq = tid & 15;
            float4 v = *(const float4*)(W + (long)(k0 + k) * COUT_ + colq * 4);
            *(float4*)&Ws[k][colq * 4] = v;
        }
        __syncthreads();

        #pragma unroll
        for (int kk = 0; kk < 16; kk++) {
            ulonglong2 a01 = *(const ulonglong2*)&Xs2[kk][trow * 8 + 0];
            ulonglong2 a23 = *(const ulonglong2*)&Xs2[kk][trow * 8 + 2];
            ulonglong2 a45 = *(const ulonglong2*)&Xs2[kk][trow * 8 + 4];
            ulonglong2 a67 = *(const ulonglong2*)&Xs2[kk][trow * 8 + 6];
            ulonglong2 b   = *(const ulonglong2*)&Ws[kk][tcol * 4];
            FMA2(acc[0][0], a01.x, b.x);  FMA2(acc[0][1], a01.x, b.y);
            FMA2(acc[1][0], a01.y, b.x);  FMA2(acc[1][1], a01.y, b.y);
            FMA2(acc[2][0], a23.x, b.x);  FMA2(acc[2][1], a23.x, b.y);
            FMA2(acc[3][0], a23.y, b.x);  FMA2(acc[3][1], a23.y, b.y);
            FMA2(acc[4][0], a45.x, b.x);  FMA2(acc[4][1], a45.x, b.y);
            FMA2(acc[5][0], a45.y, b.x);  FMA2(acc[5][1], a45.y, b.y);
            FMA2(acc[6][0], a67.x, b.x);  FMA2(acc[6][1], a67.x, b.y);
            FMA2(acc[7][0], a67.y, b.x);  FMA2(acc[7][1], a67.y, b.y);
        }
        __syncthreads();
    }

    float4 bb = *(const float4*)(bias + tcol * 4);
    #pragma unroll
    for (int r = 0; r < 8; r++) {
        int row = row0 + trow * 8 + r;
        if (row < n) {
            float2 lo = *(const float2*)&acc[r][0];
            float2 hi = *(const float2*)&acc[r][1];
            float4 o;
            o.x = lo.x + bb.x;  o.y = lo.y + bb.y;
            o.z = hi.x + bb.z;  o.w = hi.y + bb.w;
            *(float4*)&g_H[(long)row * COUT_ + tcol * 4] = o;
        }
    }
}

// ---------------------------------------------------------------------------
// B) dinv = rsqrt(1+deg); also rotate+reset the spill counter
// ---------------------------------------------------------------------------
__global__ void dinv_kernel(int n) {
    int i = blockIdx.x * blockDim.x + threadIdx.x;
    if (i < n) g_dinv[i] = rsqrtf(1.0f + (float)g_deg[i]);
    if (i == 0) {
        int s = g_spill_n;
        g_spill_n2 = (s < SPILLMAX) ? s : SPILLMAX;
        g_spill_n  = 0;                 // restore invariant for next call
    }
}

// ---------------------------------------------------------------------------
// C) gather: one warp per node, float2 per lane (64 cols)
//    out[d] = relu( sum_e dinv[s]*dinv[d]*H[s] + H[d]*dinv[d]^2 )
//    Also resets g_deg[node] = 0 (restores invariant).
// ---------------------------------------------------------------------------
__global__ __launch_bounds__(256) void gather_kernel(float* __restrict__ out, int n) {
    int node = (blockIdx.x * 256 + threadIdx.x) >> 5;
    if (node >= n) return;
    int lane = threadIdx.x & 31;

    float dd = g_dinv[node];
    int   m  = g_deg[node];
    if (lane == 0) g_deg[node] = 0;     // restore invariant
    int   mm = min(m, CAP);

    long off = (long)node * COUT_ + lane * 2;
    float2 h = *(const float2*)&g_H[off];
    float self = dd * dd;
    float2 acc = make_float2(h.x * self, h.y * self);

    const int* ep = &g_edgeb[node * CAP];
    int j = 0;
    for (; j + 4 <= mm; j += 4) {
        int4 e = *(const int4*)(ep + j);
        float c0 = __ldg(&g_dinv[e.x]) * dd;
        float c1 = __ldg(&g_dinv[e.y]) * dd;
        float c2 = __ldg(&g_dinv[e.z]) * dd;
        float c3 = __ldg(&g_dinv[e.w]) * dd;
        float2 h0 = *(const float2*)&g_H[(long)e.x * COUT_ + lane * 2];
        float2 h1 = *(const float2*)&g_H[(long)e.y * COUT_ + lane * 2];
        float2 h2 = *(const float2*)&g_H[(long)e.z * COUT_ + lane * 2];
        float2 h3 = *(const float2*)&g_H[(long)e.w * COUT_ + lane * 2];
        acc.x = fmaf(h0.x, c0, acc.x); acc.y = fmaf(h0.y, c0, acc.y);
        acc.x = fmaf(h1.x, c1, acc.x); acc.y = fmaf(h1.y, c1, acc.y);
        acc.x = fmaf(h2.x, c2, acc.x); acc.y = fmaf(h2.y, c2, acc.y);
        acc.x = fmaf(h3.x, c3, acc.x); acc.y = fmaf(h3.y, c3, acc.y);
    }
    for (; j < mm; j++) {
        int e = ep[j];
        float co = __ldg(&g_dinv[e]) * dd;
        float2 hh = *(const float2*)&g_H[(long)e * COUT_ + lane * 2];
        acc.x = fmaf(hh.x, co, acc.x); acc.y = fmaf(hh.y, co, acc.y);
    }

    // overflow edges (expected 0 entries; one broadcast load per warp)
    int ns = g_spill_n2;
    for (int i = 0; i < ns; i++) {
        int2 sp = g_spill[i];
        if (sp.x == node) {
            float co = __ldg(&g_dinv[sp.y]) * dd;
            float2 hh = *(const float2*)&g_H[(long)sp.y * COUT_ + lane * 2];
            acc.x = fmaf(hh.x, co, acc.x); acc.y = fmaf(hh.y, co, acc.y);
        }
    }

    float2 o = make_float2(fmaxf(acc.x, 0.0f), fmaxf(acc.y, 0.0f));
    *(float2*)&out[off] = o;
}

// ---------------------------------------------------------------------------
extern "C" void kernel_launch(void* const* d_in, const int* in_sizes, int n_in,
                              void* d_out, int out_size)
{
    const float* X    = (const float*)d_in[0];   // (N, 128)
    const float* W    = (const float*)d_in[1];   // (128, 64)
    const float* bias = (const float*)d_in[2];   // (64,)
    const int*   src  = (const int*)d_in[3];     // (E,)
    const int*   dst  = (const int*)d_in[4];     // (E,)
    float*       out  = (float*)d_out;           // (N, 64)

    const int n = in_sizes[0] / CIN_;
    const int E = in_sizes[3];

    const int NG = (n + 127) / 128;       // gemm tiles
    const int NE = (NG + 1) / 2;          // edge blocks (1 per 2 gemm blocks)
    const int grid = 3 * NE;

    // A) GEMM + edge bucketing, overlapped via block roles
    fused_kernel<<<grid, 256>>>(X, W, bias, src, dst, n, E, NG, NE);
    // B) dinv + spill-counter rotate
    dinv_kernel<<<(n + 255) / 256, 256>>>(n);
    // C) gather + ReLU (+deg reset)
    gather_kernel<<<(int)(((long)n * 32 + 255) / 256), 256>>>(out, n);
}

// round 5
// speedup vs baseline: 2.0145x; 2.0145x over previous
#include <cuda_runtime.h>
#include <cuda_bf16.h>

#define NMAX   100000
#define EMAX   1600000
#define CIN_   128
#define COUT_  64
#define SCAN_C 1024
#define NBLK_MAX 128

// Scratch (device globals — no allocation allowed).
// Invariants at entry (restored each call; static zero-init on first call):
//   g_deg == 0, g_scan_cnt == 0.
__device__ float g_H[NMAX * COUT_];
__device__ float g_dinv[NMAX];
__device__ int   g_deg[NMAX];
__device__ int   g_rowoff[NMAX];       // block-local exclusive prefix
__device__ int   g_boff[NBLK_MAX];     // per-1024-chunk global offset
__device__ int   g_bsum[NBLK_MAX];
__device__ int   g_pos[EMAX];
__device__ int   g_edge[EMAX];         // src only, CSR by dst
__device__ int   g_scan_cnt;

// ---------------------------------------------------------------------------
// 1) degree count + slot record, 4 edges/thread
// ---------------------------------------------------------------------------
__global__ __launch_bounds__(256) void degpos_kernel(const int* __restrict__ dst, int E) {
    int base = (blockIdx.x * 256 + threadIdx.x) * 4;
    if (base + 3 < E) {
        int4 d = *(const int4*)(dst + base);
        int4 p;
        p.x = atomicAdd(&g_deg[d.x], 1);
        p.y = atomicAdd(&g_deg[d.y], 1);
        p.z = atomicAdd(&g_deg[d.z], 1);
        p.w = atomicAdd(&g_deg[d.w], 1);
        *(int4*)(g_pos + base) = p;
    } else {
        for (int i = base; i < E; i++)
            g_pos[i] = atomicAdd(&g_deg[dst[i]], 1);
    }
}

// ---------------------------------------------------------------------------
// 2) GEMM: H = X @ W + b — packed fma.rn.f32x2, 128x64 tile, 256 threads
// ---------------------------------------------------------------------------
#define FMA2(d, a, b) asm("fma.rn.f32x2 %0, %1, %2, %3;" \
                          : "=l"(d) : "l"(a), "l"(b), "l"(d))

__global__ __launch_bounds__(256) void gemm_kernel(
    const float* __restrict__ X, const float* __restrict__ W,
    const float* __restrict__ bias, int n)
{
    __shared__ float2 Xs2[16][130];
    __shared__ float  Ws[16][64];

    const int tid  = threadIdx.x;
    const int tcol = tid & 15;
    const int trow = tid >> 4;
    const int row0 = blockIdx.x * 128;

    unsigned long long acc[8][2];
    #pragma unroll
    for (int r = 0; r < 8; r++) { acc[r][0] = 0ull; acc[r][1] = 0ull; }

    for (int k0 = 0; k0 < CIN_; k0 += 16) {
        #pragma unroll
        for (int p = 0; p < 2; p++) {
            int r  = p * 64 + (tid >> 2);
            int kq = tid & 3;
            int rr = row0 + r;
            const float* xp = X + (long)(rr < n ? rr : 0) * CIN_ + k0 + kq * 4;
            float4 v = *(const float4*)xp;
            Xs2[kq * 4 + 0][r] = make_float2(v.x, v.x);
            Xs2[kq * 4 + 1][r] = make_float2(v.y, v.y);
            Xs2[kq * 4 + 2][r] = make_float2(v.z, v.z);
            Xs2[kq * 4 + 3][r] = make_float2(v.w, v.w);
        }
        {
            int k    = tid >> 4;
            int colq = tid & 15;
            float4 v = *(const float4*)(W + (long)(k0 + k) * COUT_ + colq * 4);
            *(float4*)&Ws[k][colq * 4] = v;
        }
        __syncthreads();

        #pragma unroll
        for (int kk = 0; kk < 16; kk++) {
            ulonglong2 a01 = *(const ulonglong2*)&Xs2[kk][trow * 8 + 0];
            ulonglong2 a23 = *(const ulonglong2*)&Xs2[kk][trow * 8 + 2];
            ulonglong2 a45 = *(const ulonglong2*)&Xs2[kk][trow * 8 + 4];
            ulonglong2 a67 = *(const ulonglong2*)&Xs2[kk][trow * 8 + 6];
            ulonglong2 b   = *(const ulonglong2*)&Ws[kk][tcol * 4];
            FMA2(acc[0][0], a01.x, b.x);  FMA2(acc[0][1], a01.x, b.y);
            FMA2(acc[1][0], a01.y, b.x);  FMA2(acc[1][1], a01.y, b.y);
            FMA2(acc[2][0], a23.x, b.x);  FMA2(acc[2][1], a23.x, b.y);
            FMA2(acc[3][0], a23.y, b.x);  FMA2(acc[3][1], a23.y, b.y);
            FMA2(acc[4][0], a45.x, b.x);  FMA2(acc[4][1], a45.x, b.y);
            FMA2(acc[5][0], a45.y, b.x);  FMA2(acc[5][1], a45.y, b.y);
            FMA2(acc[6][0], a67.x, b.x);  FMA2(acc[6][1], a67.x, b.y);
            FMA2(acc[7][0], a67.y, b.x);  FMA2(acc[7][1], a67.y, b.y);
        }
        __syncthreads();
    }

    float4 bb = *(const float4*)(bias + tcol * 4);
    #pragma unroll
    for (int r = 0; r < 8; r++) {
        int row = row0 + trow * 8 + r;
        if (row < n) {
            float2 lo = *(const float2*)&acc[r][0];
            float2 hi = *(const float2*)&acc[r][1];
            float4 o;
            o.x = lo.x + bb.x;  o.y = lo.y + bb.y;
            o.z = hi.x + bb.z;  o.w = hi.y + bb.w;
            *(float4*)&g_H[(long)row * COUT_ + tcol * 4] = o;
        }
    }
}

// ---------------------------------------------------------------------------
// 3) scan: block-local exclusive prefix of deg, dinv=rsqrt(1+deg), deg:=0;
//    last-finishing block scans the <=128 block sums into g_boff.
// ---------------------------------------------------------------------------
__global__ __launch_bounds__(256) void scan_kernel(int n) {
    __shared__ int wsum[8];
    __shared__ int is_last;
    const int b    = blockIdx.x;
    const int base = b * SCAN_C + threadIdx.x * 4;
    const int lane = threadIdx.x & 31;
    const int warp = threadIdx.x >> 5;

    int v[4];
    #pragma unroll
    for (int i = 0; i < 4; i++) {
        int idx = base + i;
        v[i] = (idx < n) ? g_deg[idx] : 0;
        if (idx < n) {
            g_dinv[idx] = rsqrtf(1.0f + (float)v[i]);
            g_deg[idx]  = 0;                    // restore invariant
        }
    }
    int tsum = v[0] + v[1] + v[2] + v[3];

    int x = tsum;
    #pragma unroll
    for (int off = 1; off < 32; off <<= 1) {
        int y = __shfl_up_sync(0xFFFFFFFFu, x, off);
        if (lane >= off) x += y;
    }
    if (lane == 31) wsum[warp] = x;
    __syncthreads();
    if (threadIdx.x == 0) {
        int run = 0;
        #pragma unroll
        for (int w = 0; w < 8; w++) { int t = wsum[w]; wsum[w] = run; run += t; }
        g_bsum[b] = run;
    }
    __syncthreads();

    int run = wsum[warp] + x - tsum;
    #pragma unroll
    for (int i = 0; i < 4; i++) {
        int idx = base + i;
        if (idx < n) g_rowoff[idx] = run;
        run += v[i];
    }

    // elect last-finishing block to produce g_boff
    if (threadIdx.x == 0) {
        __threadfence();
        int old = atomicAdd(&g_scan_cnt, 1);
        is_last = (old == (int)gridDim.x - 1);
    }
    __syncthreads();
    if (is_last) {
        __threadfence();
        __shared__ int sp[NBLK_MAX];
        const int t = threadIdx.x;
        const int nblk = gridDim.x;
        if (t < NBLK_MAX) sp[t] = (t < nblk) ? g_bsum[t] : 0;
        __syncthreads();
        #pragma unroll
        for (int s = 1; s < NBLK_MAX; s <<= 1) {
            int vv = 0;
            if (t < NBLK_MAX && t >= s) vv = sp[t - s];
            __syncthreads();
            if (t < NBLK_MAX) sp[t] += vv;
            __syncthreads();
        }
        if (t < nblk) g_boff[t] = (t == 0) ? 0 : sp[t - 1];
        if (t == 0) g_scan_cnt = 0;             // restore invariant
    }
}

// ---------------------------------------------------------------------------
// 4) CSR fill (atomic-free): edge[rowoff[d]+boff[d>>10]+pos] = src, x4/thread
// ---------------------------------------------------------------------------
__global__ __launch_bounds__(256) void fill_kernel(
    const int* __restrict__ src, const int* __restrict__ dst, int E)
{
    int base = (blockIdx.x * 256 + threadIdx.x) * 4;
    if (base + 3 < E) {
        int4 s = *(const int4*)(src + base);
        int4 d = *(const int4*)(dst + base);
        int4 p = *(const int4*)(g_pos + base);
        int r0 = g_rowoff[d.x], r1 = g_rowoff[d.y];
        int r2 = g_rowoff[d.z], r3 = g_rowoff[d.w];
        int b0 = g_boff[d.x >> 10], b1 = g_boff[d.y >> 10];
        int b2 = g_boff[d.z >> 10], b3 = g_boff[d.w >> 10];
        g_edge[r0 + b0 + p.x] = s.x;
        g_edge[r1 + b1 + p.y] = s.y;
        g_edge[r2 + b2 + p.z] = s.z;
        g_edge[r3 + b3 + p.w] = s.w;
    } else {
        for (int i = base; i < E; i++) {
            int d = dst[i];
            g_edge[g_rowoff[d] + g_boff[d >> 10] + g_pos[i]] = src[i];
        }
    }
}

// ---------------------------------------------------------------------------
// 5) gather: one warp per node, float2 per lane (64 cols)
//    out[d] = relu( sum_e dinv[s]*dinv[d]*H[s] + H[d]*dinv[d]^2 )
// ---------------------------------------------------------------------------
__global__ __launch_bounds__(256) void gather_kernel(float* __restrict__ out,
                                                     int n, int E) {
    int node = (blockIdx.x * 256 + threadIdx.x) >> 5;
    if (node >= n) return;
    int lane = threadIdx.x & 31;

    float dd = g_dinv[node];
    int   r0 = g_rowoff[node] + g_boff[node >> 10];
    int   r1 = (node + 1 < n) ? (g_rowoff[node + 1] + g_boff[(node + 1) >> 10]) : E;
    int   m  = r1 - r0;

    long off = (long)node * COUT_ + lane * 2;
    float2 h = *(const float2*)&g_H[off];
    float self = dd * dd;
    float2 acc = make_float2(h.x * self, h.y * self);

    const int* ep = &g_edge[r0];
    int j = 0;
    for (; j + 4 <= m; j += 4) {
        int e0 = __ldg(ep + j),     e1 = __ldg(ep + j + 1);
        int e2 = __ldg(ep + j + 2), e3 = __ldg(ep + j + 3);
        float c0 = __ldg(&g_dinv[e0]) * dd;
        float c1 = __ldg(&g_dinv[e1]) * dd;
        float c2 = __ldg(&g_dinv[e2]) * dd;
        float c3 = __ldg(&g_dinv[e3]) * dd;
        float2 h0 = *(const float2*)&g_H[(long)e0 * COUT_ + lane * 2];
        float2 h1 = *(const float2*)&g_H[(long)e1 * COUT_ + lane * 2];
        float2 h2 = *(const float2*)&g_H[(long)e2 * COUT_ + lane * 2];
        float2 h3 = *(const float2*)&g_H[(long)e3 * COUT_ + lane * 2];
        acc.x = fmaf(h0.x, c0, acc.x); acc.y = fmaf(h0.y, c0, acc.y);
        acc.x = fmaf(h1.x, c1, acc.x); acc.y = fmaf(h1.y, c1, acc.y);
        acc.x = fmaf(h2.x, c2, acc.x); acc.y = fmaf(h2.y, c2, acc.y);
        acc.x = fmaf(h3.x, c3, acc.x); acc.y = fmaf(h3.y, c3, acc.y);
    }
    for (; j < m; j++) {
        int e = __ldg(ep + j);
        float co = __ldg(&g_dinv[e]) * dd;
        float2 hh = *(const float2*)&g_H[(long)e * COUT_ + lane * 2];
        acc.x = fmaf(hh.x, co, acc.x); acc.y = fmaf(hh.y, co, acc.y);
    }

    float2 o = make_float2(fmaxf(acc.x, 0.0f), fmaxf(acc.y, 0.0f));
    *(float2*)&out[off] = o;
}

// ---------------------------------------------------------------------------
extern "C" void kernel_launch(void* const* d_in, const int* in_sizes, int n_in,
                              void* d_out, int out_size)
{
    const float* X    = (const float*)d_in[0];   // (N, 128)
    const float* W    = (const float*)d_in[1];   // (128, 64)
    const float* bias = (const float*)d_in[2];   // (64,)
    const int*   src  = (const int*)d_in[3];     // (E,)
    const int*   dst  = (const int*)d_in[4];     // (E,)
    float*       out  = (float*)d_out;           // (N, 64)

    const int n = in_sizes[0] / CIN_;
    const int E = in_sizes[3];
    const int nblk = (n + SCAN_C - 1) / SCAN_C;

    degpos_kernel<<<(E + 1023) / 1024, 256>>>(dst, E);
    gemm_kernel<<<(n + 127) / 128, 256>>>(X, W, bias, n);
    scan_kernel<<<nblk, 256>>>(n);
    fill_kernel<<<(E + 1023) / 1024, 256>>>(src, dst, E);
    gather_kernel<<<(int)(((long)n * 32 + 255) / 256), 256>>>(out, n, E);
}

// round 6
// speedup vs baseline: 2.0408x; 1.0131x over previous
#include <cuda_runtime.h>
#include <cuda_fp16.h>

#define NMAX   100000
#define EMAX   1600000
#define CIN_   128
#define COUT_  64
#define SCAN_C 1024
#define NBLK_MAX 128

// Scratch (device globals — no allocation allowed).
// Invariants at entry (restored each call; static zero-init on first call):
//   g_deg == 0, g_scan_cnt == 0.
__device__ __half2 g_H2[NMAX * (COUT_ / 2)];   // H in fp16, 32 half2 per row
__device__ float   g_dinv[NMAX];
__device__ int     g_deg[NMAX];
__device__ int     g_rowoff[NMAX];             // block-local exclusive prefix
__device__ int     g_boff[NBLK_MAX];           // per-1024-chunk global offset
__device__ int     g_bsum[NBLK_MAX];
__device__ int     g_pos[EMAX];
__device__ int2    g_edge[EMAX];               // {src, bitcast(dinv[src])}
__device__ int     g_scan_cnt;

// ---------------------------------------------------------------------------
// 1) degree count + slot record, 8 edges/thread (2x int4) for MLP
// ---------------------------------------------------------------------------
__global__ __launch_bounds__(256) void degpos_kernel(const int* __restrict__ dst, int E) {
    int base = (blockIdx.x * 256 + threadIdx.x) * 8;
    if (base + 7 < E) {
        int4 d0 = *(const int4*)(dst + base);
        int4 d1 = *(const int4*)(dst + base + 4);
        int4 p0, p1;
        p0.x = atomicAdd(&g_deg[d0.x], 1);
        p0.y = atomicAdd(&g_deg[d0.y], 1);
        p0.z = atomicAdd(&g_deg[d0.z], 1);
        p0.w = atomicAdd(&g_deg[d0.w], 1);
        p1.x = atomicAdd(&g_deg[d1.x], 1);
        p1.y = atomicAdd(&g_deg[d1.y], 1);
        p1.z = atomicAdd(&g_deg[d1.z], 1);
        p1.w = atomicAdd(&g_deg[d1.w], 1);
        *(int4*)(g_pos + base)     = p0;
        *(int4*)(g_pos + base + 4) = p1;
    } else {
        for (int i = base; i < E; i++)
            g_pos[i] = atomicAdd(&g_deg[dst[i]], 1);
    }
}

// ---------------------------------------------------------------------------
// 2) GEMM: H = X @ W + b — packed fma.rn.f32x2, 128x64 tile, 256 threads
//    epilogue converts to half2
// ---------------------------------------------------------------------------
#define FMA2(d, a, b) asm("fma.rn.f32x2 %0, %1, %2, %3;" \
                          : "=l"(d) : "l"(a), "l"(b), "l"(d))

__global__ __launch_bounds__(256) void gemm_kernel(
    const float* __restrict__ X, const float* __restrict__ W,
    const float* __restrict__ bias, int n)
{
    __shared__ float2 Xs2[16][130];
    __shared__ float  Ws[16][64];

    const int tid  = threadIdx.x;
    const int tcol = tid & 15;
    const int trow = tid >> 4;
    const int row0 = blockIdx.x * 128;

    unsigned long long acc[8][2];
    #pragma unroll
    for (int r = 0; r < 8; r++) { acc[r][0] = 0ull; acc[r][1] = 0ull; }

    for (int k0 = 0; k0 < CIN_; k0 += 16) {
        #pragma unroll
        for (int p = 0; p < 2; p++) {
            int r  = p * 64 + (tid >> 2);
            int kq = tid & 3;
            int rr = row0 + r;
            const float* xp = X + (long)(rr < n ? rr : 0) * CIN_ + k0 + kq * 4;
            float4 v = *(const float4*)xp;
            Xs2[kq * 4 + 0][r] = make_float2(v.x, v.x);
            Xs2[kq * 4 + 1][r] = make_float2(v.y, v.y);
            Xs2[kq * 4 + 2][r] = make_float2(v.z, v.z);
            Xs2[kq * 4 + 3][r] = make_float2(v.w, v.w);
        }
        {
            int k    = tid >> 4;
            int colq = tid & 15;
            float4 v = *(const float4*)(W + (long)(k0 + k) * COUT_ + colq * 4);
            *(float4*)&Ws[k][colq * 4] = v;
        }
        __syncthreads();

        #pragma unroll
        for (int kk = 0; kk < 16; kk++) {
            ulonglong2 a01 = *(const ulonglong2*)&Xs2[kk][trow * 8 + 0];
            ulonglong2 a23 = *(const ulonglong2*)&Xs2[kk][trow * 8 + 2];
            ulonglong2 a45 = *(const ulonglong2*)&Xs2[kk][trow * 8 + 4];
            ulonglong2 a67 = *(const ulonglong2*)&Xs2[kk][trow * 8 + 6];
            ulonglong2 b   = *(const ulonglong2*)&Ws[kk][tcol * 4];
            FMA2(acc[0][0], a01.x, b.x);  FMA2(acc[0][1], a01.x, b.y);
            FMA2(acc[1][0], a01.y, b.x);  FMA2(acc[1][1], a01.y, b.y);
            FMA2(acc[2][0], a23.x, b.x);  FMA2(acc[2][1], a23.x, b.y);
            FMA2(acc[3][0], a23.y, b.x);  FMA2(acc[3][1], a23.y, b.y);
            FMA2(acc[4][0], a45.x, b.x);  FMA2(acc[4][1], a45.x, b.y);
            FMA2(acc[5][0], a45.y, b.x);  FMA2(acc[5][1], a45.y, b.y);
            FMA2(acc[6][0], a67.x, b.x);  FMA2(acc[6][1], a67.x, b.y);
            FMA2(acc[7][0], a67.y, b.x);  FMA2(acc[7][1], a67.y, b.y);
        }
        __syncthreads();
    }

    float2 bb0 = *(const float2*)(bias + tcol * 4);
    float2 bb1 = *(const float2*)(bias + tcol * 4 + 2);
    #pragma unroll
    for (int r = 0; r < 8; r++) {
        int row = row0 + trow * 8 + r;
        if (row < n) {
            float2 lo = *(const float2*)&acc[r][0];
            float2 hi = *(const float2*)&acc[r][1];
            __half2 h0 = __floats2half2_rn(lo.x + bb0.x, lo.y + bb0.y);
            __half2 h1 = __floats2half2_rn(hi.x + bb1.x, hi.y + bb1.y);
            g_H2[(long)row * 32 + tcol * 2]     = h0;
            g_H2[(long)row * 32 + tcol * 2 + 1] = h1;
        }
    }
}

// ---------------------------------------------------------------------------
// 3) scan: block-local exclusive prefix of deg, dinv=rsqrt(1+deg), deg:=0;
//    last-finishing block scans the <=128 block sums into g_boff.
// ---------------------------------------------------------------------------
__global__ __launch_bounds__(256) void scan_kernel(int n) {
    __shared__ int wsum[8];
    __shared__ int is_last;
    const int b    = blockIdx.x;
    const int base = b * SCAN_C + threadIdx.x * 4;
    const int lane = threadIdx.x & 31;
    const int warp = threadIdx.x >> 5;

    int v[4];
    #pragma unroll
    for (int i = 0; i < 4; i++) {
        int idx = base + i;
        v[i] = (idx < n) ? g_deg[idx] : 0;
        if (idx < n) {
            g_dinv[idx] = rsqrtf(1.0f + (float)v[i]);
            g_deg[idx]  = 0;                    // restore invariant
        }
    }
    int tsum = v[0] + v[1] + v[2] + v[3];

    int x = tsum;
    #pragma unroll
    for (int off = 1; off < 32; off <<= 1) {
        int y = __shfl_up_sync(0xFFFFFFFFu, x, off);
        if (lane >= off) x += y;
    }
    if (lane == 31) wsum[warp] = x;
    __syncthreads();
    if (threadIdx.x == 0) {
        int run = 0;
        #pragma unroll
        for (int w = 0; w < 8; w++) { int t = wsum[w]; wsum[w] = run; run += t; }
        g_bsum[b] = run;
    }
    __syncthreads();

    int run = wsum[warp] + x - tsum;
    #pragma unroll
    for (int i = 0; i < 4; i++) {
        int idx = base + i;
        if (idx < n) g_rowoff[idx] = run;
        run += v[i];
    }

    if (threadIdx.x == 0) {
        __threadfence();
        int old = atomicAdd(&g_scan_cnt, 1);
        is_last = (old == (int)gridDim.x - 1);
    }
    __syncthreads();
    if (is_last) {
        __threadfence();
        __shared__ int sp[NBLK_MAX];
        const int t = threadIdx.x;
        const int nblk = gridDim.x;
        if (t < NBLK_MAX) sp[t] = (t < nblk) ? g_bsum[t] : 0;
        __syncthreads();
        #pragma unroll
        for (int s = 1; s < NBLK_MAX; s <<= 1) {
            int vv = 0;
            if (t < NBLK_MAX && t >= s) vv = sp[t - s];
            __syncthreads();
            if (t < NBLK_MAX) sp[t] += vv;
            __syncthreads();
        }
        if (t < nblk) g_boff[t] = (t == 0) ? 0 : sp[t - 1];
        if (t == 0) g_scan_cnt = 0;             // restore invariant
    }
}

// ---------------------------------------------------------------------------
// 4) CSR fill (atomic-free): edge[glob_rowoff(d)+pos] = {src, dinv[src]},
//    8 edges/thread
// ---------------------------------------------------------------------------
__global__ __launch_bounds__(256) void fill_kernel(
    const int* __restrict__ src, const int* __restrict__ dst, int E)
{
    int base = (blockIdx.x * 256 + threadIdx.x) * 8;
    if (base + 7 < E) {
        #pragma unroll
        for (int q = 0; q < 2; q++) {
            int4 s = *(const int4*)(src + base + q * 4);
            int4 d = *(const int4*)(dst + base + q * 4);
            int4 p = *(const int4*)(g_pos + base + q * 4);
            int o0 = g_rowoff[d.x] + g_boff[d.x >> 10] + p.x;
            int o1 = g_rowoff[d.y] + g_boff[d.y >> 10] + p.y;
            int o2 = g_rowoff[d.z] + g_boff[d.z >> 10] + p.z;
            int o3 = g_rowoff[d.w] + g_boff[d.w >> 10] + p.w;
            float f0 = g_dinv[s.x], f1 = g_dinv[s.y];
            float f2 = g_dinv[s.z], f3 = g_dinv[s.w];
            g_edge[o0] = make_int2(s.x, __float_as_int(f0));
            g_edge[o1] = make_int2(s.y, __float_as_int(f1));
            g_edge[o2] = make_int2(s.z, __float_as_int(f2));
            g_edge[o3] = make_int2(s.w, __float_as_int(f3));
        }
    } else {
        for (int i = base; i < E; i++) {
            int d = dst[i];
            int s = src[i];
            g_edge[g_rowoff[d] + g_boff[d >> 10] + g_pos[i]] =
                make_int2(s, __float_as_int(g_dinv[s]));
        }
    }
}

// ---------------------------------------------------------------------------
// 5) gather: one warp per node, one half2 per lane (64 cols), fp32 accum
//    out[d] = relu( sum_e dinv[s]*dinv[d]*H[s] + H[d]*dinv[d]^2 )
// ---------------------------------------------------------------------------
__global__ __launch_bounds__(256) void gather_kernel(float* __restrict__ out,
                                                     int n, int E) {
    int node = (blockIdx.x * 256 + threadIdx.x) >> 5;
    if (node >= n) return;
    int lane = threadIdx.x & 31;

    float dd = g_dinv[node];
    int   r0 = g_rowoff[node] + g_boff[node >> 10];
    int   r1 = (node + 1 < n) ? (g_rowoff[node + 1] + g_boff[(node + 1) >> 10]) : E;
    int   m  = r1 - r0;

    float2 h = __half22float2(g_H2[(long)node * 32 + lane]);
    float self = dd * dd;
    float2 acc = make_float2(h.x * self, h.y * self);

    const int2* ep = &g_edge[r0];
    int j = 0;
    for (; j + 4 <= m; j += 4) {
        int2 e0 = __ldg(ep + j),     e1 = __ldg(ep + j + 1);
        int2 e2 = __ldg(ep + j + 2), e3 = __ldg(ep + j + 3);
        float2 h0 = __half22float2(g_H2[(long)e0.x * 32 + lane]);
        float2 h1 = __half22float2(g_H2[(long)e1.x * 32 + lane]);
        float2 h2 = __half22float2(g_H2[(long)e2.x * 32 + lane]);
        float2 h3 = __half22float2(g_H2[(long)e3.x * 32 + lane]);
        float c0 = __int_as_float(e0.y) * dd;
        float c1 = __int_as_float(e1.y) * dd;
        float c2 = __int_as_float(e2.y) * dd;
        float c3 = __int_as_float(e3.y) * dd;
        acc.x = fmaf(h0.x, c0, acc.x); acc.y = fmaf(h0.y, c0, acc.y);
        acc.x = fmaf(h1.x, c1, acc.x); acc.y = fmaf(h1.y, c1, acc.y);
        acc.x = fmaf(h2.x, c2, acc.x); acc.y = fmaf(h2.y, c2, acc.y);
        acc.x = fmaf(h3.x, c3, acc.x); acc.y = fmaf(h3.y, c3, acc.y);
    }
    for (; j < m; j++) {
        int2 e = __ldg(ep + j);
        float co = __int_as_float(e.y) * dd;
        float2 hh = __half22float2(g_H2[(long)e.x * 32 + lane]);
        acc.x = fmaf(hh.x, co, acc.x); acc.y = fmaf(hh.y, co, acc.y);
    }

    float2 o = make_float2(fmaxf(acc.x, 0.0f), fmaxf(acc.y, 0.0f));
    *(float2*)&out[(long)node * COUT_ + lane * 2] = o;
}

// ---------------------------------------------------------------------------
extern "C" void kernel_launch(void* const* d_in, const int* in_sizes, int n_in,
                              void* d_out, int out_size)
{
    const float* X    = (const float*)d_in[0];   // (N, 128)
    const float* W    = (const float*)d_in[1];   // (128, 64)
    const float* bias = (const float*)d_in[2];   // (64,)
    const int*   src  = (const int*)d_in[3];     // (E,)
    const int*   dst  = (const int*)d_in[4];     // (E,)
    float*       out  = (float*)d_out;           // (N, 64)

    const int n = in_sizes[0] / CIN_;
    const int E = in_sizes[3];
    const int nblk = (n + SCAN_C - 1) / SCAN_C;

    degpos_kernel<<<(E + 2047) / 2048, 256>>>(dst, E);
    gemm_kernel<<<(n + 127) / 128, 256>>>(X, W, bias, n);
    scan_kernel<<<nblk, 256>>>(n);
    fill_kernel<<<(E + 2047) / 2048, 256>>>(src, dst, E);
    gather_kernel<<<(int)(((long)n * 32 + 255) / 256), 256>>>(out, n, E);
}

// round 7
// speedup vs baseline: 2.1326x; 1.0450x over previous
#include <cuda_runtime.h>
#include <cuda_fp16.h>

#define NMAX   100000
#define EMAX   1600000
#define CIN_   128
#define COUT_  64
#define SCAN_C 1024
#define NBLK_MAX 128

// Scratch (device globals — no allocation allowed).
// Invariants at entry (restored each call; static zero-init on first call):
//   g_deg == 0, g_scan_cnt == 0.
__device__ __half2 g_H2[NMAX * (COUT_ / 2)];   // Hs = (X@W+b)*dinv, fp16
__device__ float   g_dinv[NMAX];
__device__ int     g_deg[NMAX];
__device__ int     g_rowoff[NMAX];             // block-local exclusive prefix
__device__ int     g_boff[NBLK_MAX];           // per-1024-chunk global offset
__device__ int     g_bsum[NBLK_MAX];
__device__ int     g_pos[EMAX];
__device__ int     g_edge[EMAX];               // src only, CSR by dst
__device__ int     g_scan_cnt;

// ---------------------------------------------------------------------------
// 1) degree count + slot record, 4 edges/thread
// ---------------------------------------------------------------------------
__global__ __launch_bounds__(256) void degpos_kernel(const int* __restrict__ dst, int E) {
    int base = (blockIdx.x * 256 + threadIdx.x) * 4;
    if (base + 3 < E) {
        int4 d = *(const int4*)(dst + base);
        int4 p;
        p.x = atomicAdd(&g_deg[d.x], 1);
        p.y = atomicAdd(&g_deg[d.y], 1);
        p.z = atomicAdd(&g_deg[d.z], 1);
        p.w = atomicAdd(&g_deg[d.w], 1);
        *(int4*)(g_pos + base) = p;
    } else {
        for (int i = base; i < E; i++)
            g_pos[i] = atomicAdd(&g_deg[dst[i]], 1);
    }
}

// ---------------------------------------------------------------------------
// 2) scan: block-local exclusive prefix of deg, dinv=rsqrt(1+deg), deg:=0;
//    last-finishing block scans the <=128 block sums into g_boff.
// ---------------------------------------------------------------------------
__global__ __launch_bounds__(256) void scan_kernel(int n) {
    __shared__ int wsum[8];
    __shared__ int is_last;
    const int b    = blockIdx.x;
    const int base = b * SCAN_C + threadIdx.x * 4;
    const int lane = threadIdx.x & 31;
    const int warp = threadIdx.x >> 5;

    int v[4];
    #pragma unroll
    for (int i = 0; i < 4; i++) {
        int idx = base + i;
        v[i] = (idx < n) ? g_deg[idx] : 0;
        if (idx < n) {
            g_dinv[idx] = rsqrtf(1.0f + (float)v[i]);
            g_deg[idx]  = 0;                    // restore invariant
        }
    }
    int tsum = v[0] + v[1] + v[2] + v[3];

    int x = tsum;
    #pragma unroll
    for (int off = 1; off < 32; off <<= 1) {
        int y = __shfl_up_sync(0xFFFFFFFFu, x, off);
        if (lane >= off) x += y;
    }
    if (lane == 31) wsum[warp] = x;
    __syncthreads();
    if (threadIdx.x == 0) {
        int run = 0;
        #pragma unroll
        for (int w = 0; w < 8; w++) { int t = wsum[w]; wsum[w] = run; run += t; }
        g_bsum[b] = run;
    }
    __syncthreads();

    int run = wsum[warp] + x - tsum;
    #pragma unroll
    for (int i = 0; i < 4; i++) {
        int idx = base + i;
        if (idx < n) g_rowoff[idx] = run;
        run += v[i];
    }

    if (threadIdx.x == 0) {
        __threadfence();
        int old = atomicAdd(&g_scan_cnt, 1);
        is_last = (old == (int)gridDim.x - 1);
    }
    __syncthreads();
    if (is_last) {
        __threadfence();
        __shared__ int sp[NBLK_MAX];
        const int t = threadIdx.x;
        const int nblk = gridDim.x;
        if (t < NBLK_MAX) sp[t] = (t < nblk) ? g_bsum[t] : 0;
        __syncthreads();
        #pragma unroll
        for (int s = 1; s < NBLK_MAX; s <<= 1) {
            int vv = 0;
            if (t < NBLK_MAX && t >= s) vv = sp[t - s];
            __syncthreads();
            if (t < NBLK_MAX) sp[t] += vv;
            __syncthreads();
        }
        if (t < nblk) g_boff[t] = (t == 0) ? 0 : sp[t - 1];
        if (t == 0) g_scan_cnt = 0;             // restore invariant
    }
}

// ---------------------------------------------------------------------------
// 3) GEMM: Hs = (X @ W + b) * dinv — packed fma.rn.f32x2, fp16 epilogue
// ---------------------------------------------------------------------------
#define FMA2(d, a, b) asm("fma.rn.f32x2 %0, %1, %2, %3;" \
                          : "=l"(d) : "l"(a), "l"(b), "l"(d))

__global__ __launch_bounds__(256) void gemm_kernel(
    const float* __restrict__ X, const float* __restrict__ W,
    const float* __restrict__ bias, int n)
{
    __shared__ float2 Xs2[16][130];
    __shared__ float  Ws[16][64];

    const int tid  = threadIdx.x;
    const int tcol = tid & 15;
    const int trow = tid >> 4;
    const int row0 = blockIdx.x * 128;

    unsigned long long acc[8][2];
    #pragma unroll
    for (int r = 0; r < 8; r++) { acc[r][0] = 0ull; acc[r][1] = 0ull; }

    for (int k0 = 0; k0 < CIN_; k0 += 16) {
        #pragma unroll
        for (int p = 0; p < 2; p++) {
            int r  = p * 64 + (tid >> 2);
            int kq = tid & 3;
            int rr = row0 + r;
            const float* xp = X + (long)(rr < n ? rr : 0) * CIN_ + k0 + kq * 4;
            float4 v = *(const float4*)xp;
            Xs2[kq * 4 + 0][r] = make_float2(v.x, v.x);
            Xs2[kq * 4 + 1][r] = make_float2(v.y, v.y);
            Xs2[kq * 4 + 2][r] = make_float2(v.z, v.z);
            Xs2[kq * 4 + 3][r] = make_float2(v.w, v.w);
        }
        {
            int k    = tid >> 4;
            int colq = tid & 15;
            float4 v = *(const float4*)(W + (long)(k0 + k) * COUT_ + colq * 4);
            *(float4*)&Ws[k][colq * 4] = v;
        }
        __syncthreads();

        #pragma unroll
        for (int kk = 0; kk < 16; kk++) {
            ulonglong2 a01 = *(const ulonglong2*)&Xs2[kk][trow * 8 + 0];
            ulonglong2 a23 = *(const ulonglong2*)&Xs2[kk][trow * 8 + 2];
            ulonglong2 a45 = *(const ulonglong2*)&Xs2[kk][trow * 8 + 4];
            ulonglong2 a67 = *(const ulonglong2*)&Xs2[kk][trow * 8 + 6];
            ulonglong2 b   = *(const ulonglong2*)&Ws[kk][tcol * 4];
            FMA2(acc[0][0], a01.x, b.x);  FMA2(acc[0][1], a01.x, b.y);
            FMA2(acc[1][0], a01.y, b.x);  FMA2(acc[1][1], a01.y, b.y);
            FMA2(acc[2][0], a23.x, b.x);  FMA2(acc[2][1], a23.x, b.y);
            FMA2(acc[3][0], a23.y, b.x);  FMA2(acc[3][1], a23.y, b.y);
            FMA2(acc[4][0], a45.x, b.x);  FMA2(acc[4][1], a45.x, b.y);
            FMA2(acc[5][0], a45.y, b.x);  FMA2(acc[5][1], a45.y, b.y);
            FMA2(acc[6][0], a67.x, b.x);  FMA2(acc[6][1], a67.x, b.y);
            FMA2(acc[7][0], a67.y, b.x);  FMA2(acc[7][1], a67.y, b.y);
        }
        __syncthreads();
    }

    float2 bb0 = *(const float2*)(bias + tcol * 4);
    float2 bb1 = *(const float2*)(bias + tcol * 4 + 2);
    #pragma unroll
    for (int r = 0; r < 8; r++) {
        int row = row0 + trow * 8 + r;
        if (row < n) {
            float di = g_dinv[row];           // broadcast across the 16 col threads
            float2 lo = *(const float2*)&acc[r][0];
            float2 hi = *(const float2*)&acc[r][1];
            __half2 h0 = __floats2half2_rn((lo.x + bb0.x) * di, (lo.y + bb0.y) * di);
            __half2 h1 = __floats2half2_rn((hi.x + bb1.x) * di, (hi.y + bb1.y) * di);
            g_H2[(long)row * 32 + tcol * 2]     = h0;
            g_H2[(long)row * 32 + tcol * 2 + 1] = h1;
        }
    }
}

// ---------------------------------------------------------------------------
// 4) CSR fill (atomic-free, src-only payload), 4 edges/thread
// ---------------------------------------------------------------------------
__global__ __launch_bounds__(256) void fill_kernel(
    const int* __restrict__ src, const int* __restrict__ dst, int E)
{
    int base = (blockIdx.x * 256 + threadIdx.x) * 4;
    if (base + 3 < E) {
        int4 s = *(const int4*)(src + base);
        int4 d = *(const int4*)(dst + base);
        int4 p = *(const int4*)(g_pos + base);
        int o0 = g_rowoff[d.x] + g_boff[d.x >> 10] + p.x;
        int o1 = g_rowoff[d.y] + g_boff[d.y >> 10] + p.y;
        int o2 = g_rowoff[d.z] + g_boff[d.z >> 10] + p.z;
        int o3 = g_rowoff[d.w] + g_boff[d.w >> 10] + p.w;
        g_edge[o0] = s.x;
        g_edge[o1] = s.y;
        g_edge[o2] = s.z;
        g_edge[o3] = s.w;
    } else {
        for (int i = base; i < E; i++) {
            int d = dst[i];
            g_edge[g_rowoff[d] + g_boff[d >> 10] + g_pos[i]] = src[i];
        }
    }
}

// ---------------------------------------------------------------------------
// 5) gather: one warp per node, one half2 per lane (64 cols), fp32 accum
//    out[d] = relu( dinv[d] * ( Hs[d] + sum_e Hs[src] ) )
// ---------------------------------------------------------------------------
__device__ __forceinline__ float2 ldcs_h2f2(const __half2* p) {
    unsigned u;
    asm volatile("ld.global.cs.b32 %0, [%1];" : "=r"(u) : "l"(p));
    return __half22float2(*reinterpret_cast<__half2*>(&u));
}

__global__ __launch_bounds__(256) void gather_kernel(float* __restrict__ out,
                                                     int n, int E) {
    int node = (blockIdx.x * 256 + threadIdx.x) >> 5;
    if (node >= n) return;
    int lane = threadIdx.x & 31;

    float dd = g_dinv[node];
    int   r0 = g_rowoff[node] + g_boff[node >> 10];
    int   r1 = (node + 1 < n) ? (g_rowoff[node + 1] + g_boff[(node + 1) >> 10]) : E;
    int   m  = r1 - r0;

    float2 acc = __half22float2(g_H2[(long)node * 32 + lane]);

    const int* ep = &g_edge[r0];
    int j = 0;
    for (; j + 4 <= m; j += 4) {
        int e0 = __ldg(ep + j),     e1 = __ldg(ep + j + 1);
        int e2 = __ldg(ep + j + 2), e3 = __ldg(ep + j + 3);
        float2 h0 = ldcs_h2f2(&g_H2[(long)e0 * 32 + lane]);
        float2 h1 = ldcs_h2f2(&g_H2[(long)e1 * 32 + lane]);
        float2 h2 = ldcs_h2f2(&g_H2[(long)e2 * 32 + lane]);
        float2 h3 = ldcs_h2f2(&g_H2[(long)e3 * 32 + lane]);
        acc.x += h0.x + h1.x;  acc.y += h0.y + h1.y;
        acc.x += h2.x + h3.x;  acc.y += h2.y + h3.y;
    }
    for (; j < m; j++) {
        int e = __ldg(ep + j);
        float2 hh = ldcs_h2f2(&g_H2[(long)e * 32 + lane]);
        acc.x += hh.x;  acc.y += hh.y;
    }

    float2 o = make_float2(fmaxf(acc.x * dd, 0.0f), fmaxf(acc.y * dd, 0.0f));
    *(float2*)&out[(long)node * COUT_ + lane * 2] = o;
}

// ---------------------------------------------------------------------------
extern "C" void kernel_launch(void* const* d_in, const int* in_sizes, int n_in,
                              void* d_out, int out_size)
{
    const float* X    = (const float*)d_in[0];   // (N, 128)
    const float* W    = (const float*)d_in[1];   // (128, 64)
    const float* bias = (const float*)d_in[2];   // (64,)
    const int*   src  = (const int*)d_in[3];     // (E,)
    const int*   dst  = (const int*)d_in[4];     // (E,)
    float*       out  = (float*)d_out;           // (N, 64)

    const int n = in_sizes[0] / CIN_;
    const int E = in_sizes[3];
    const int nblk = (n + SCAN_C - 1) / SCAN_C;

    degpos_kernel<<<(E + 1023) / 1024, 256>>>(dst, E);
    scan_kernel<<<nblk, 256>>>(n);
    gemm_kernel<<<(n + 127) / 128, 256>>>(X, W, bias, n);
    fill_kernel<<<(E + 1023) / 1024, 256>>>(src, dst, E);
    gather_kernel<<<(int)(((long)n * 32 + 255) / 256), 256>>>(out, n, E);
}